// round 1
// baseline (speedup 1.0000x reference)
#include <cuda_runtime.h>
#include <math.h>

// ---------------- problem constants ----------------
#define H     2048
#define E     60
#define II    1408
#define I2    2816      // 2*II
#define ISH   5632
#define ISH2  11264     // 2*ISH
#define TOPK  4
#define MAXM  1024
#define MAXSLOTS (MAXM*TOPK)

// ---------------- device scratch (static, no allocs) ----------------
static __device__ float g_gu  [MAXM * ISH2];     // shared-expert gate_up output
static __device__ float g_hsh [MAXM * ISH];      // shared-expert silu*mul
static __device__ float g_gur [MAXSLOTS * I2];   // routed gate_up output (per slot)
static __device__ float g_hr  [MAXSLOTS * II];   // routed silu*mul
static __device__ float g_y   [MAXSLOTS * H];    // routed per-pair weighted output
static __device__ float g_sig [MAXM];            // shared-expert sigmoid gate
static __device__ int   g_cnt [E];
static __device__ int   g_off [E];
static __device__ int   g_cur [E];
static __device__ int   g_slot_token[MAXSLOTS];
static __device__ float g_slot_w    [MAXSLOTS];
static __device__ int   g_slot_of   [MAXM * TOPK];
static __device__ int   g_tk_e      [MAXM * TOPK];
static __device__ float g_tk_w      [MAXM * TOPK];

// ---------------- small kernels ----------------
__global__ void zero_counts_kernel() {
    int t = threadIdx.x;
    if (t < E) g_cnt[t] = 0;
}

// One block per token: router logits + softmax + top-4 + shared sigmoid gate.
__global__ void router_kernel(const float* __restrict__ x,
                              const float* __restrict__ gate_w,
                              const float* __restrict__ sgw) {
    __shared__ float xs[H];
    __shared__ float logits[E + 1];
    int m = blockIdx.x;
    const float* xr = x + (size_t)m * H;
    for (int i = threadIdx.x; i < H; i += blockDim.x) xs[i] = xr[i];
    __syncthreads();

    int wid = threadIdx.x >> 5, lane = threadIdx.x & 31;
    for (int e = wid; e <= E; e += 8) {
        const float* wr = (e < E) ? (gate_w + (size_t)e * H) : sgw;
        float acc = 0.f;
        for (int k = lane; k < H; k += 32) acc += xs[k] * wr[k];
        #pragma unroll
        for (int o = 16; o; o >>= 1) acc += __shfl_xor_sync(0xffffffffu, acc, o);
        if (lane == 0) logits[e] = acc;
    }
    __syncthreads();

    if (threadIdx.x == 0) {
        g_sig[m] = 1.f / (1.f + expf(-logits[E]));
        float mx = -1e30f;
        for (int e = 0; e < E; e++) mx = fmaxf(mx, logits[e]);
        float sum = 0.f;
        for (int e = 0; e < E; e++) { float p = expf(logits[e] - mx); logits[e] = p; sum += p; }
        float inv = 1.f / sum;
        for (int k = 0; k < TOPK; k++) {
            int best = 0; float bv = -1.f;
            for (int e = 0; e < E; e++) { float v = logits[e]; if (v > bv) { bv = v; best = e; } }
            logits[best] = -2.f;
            g_tk_e[m * TOPK + k] = best;
            g_tk_w[m * TOPK + k] = bv * inv;   // no renormalization (Qwen2MoE)
            atomicAdd(&g_cnt[best], 1);
        }
    }
}

__global__ void scan_kernel() {
    if (threadIdx.x == 0) {
        int s = 0;
        for (int e = 0; e < E; e++) { g_off[e] = s; s += g_cnt[e]; g_cur[e] = 0; }
    }
}

__global__ void fill_kernel(int M) {
    int m = blockIdx.x * blockDim.x + threadIdx.x;
    if (m >= M) return;
    for (int k = 0; k < TOPK; k++) {
        int e = g_tk_e[m * TOPK + k];
        int pos = atomicAdd(&g_cur[e], 1);
        int slot = g_off[e] + pos;
        g_slot_token[slot] = m;
        g_slot_w[slot] = g_tk_w[m * TOPK + k];
        g_slot_of[m * TOPK + k] = slot;
    }
}

__device__ __forceinline__ float silu_f(float v) { return v / (1.f + expf(-v)); }

__global__ void silu_mul_kernel(const float* __restrict__ gu, float* __restrict__ h,
                                int rows, int half, int full) {
    int total = rows * half;
    for (int idx = blockIdx.x * blockDim.x + threadIdx.x; idx < total;
         idx += gridDim.x * blockDim.x) {
        int r = idx / half, i = idx - r * half;
        float g = gu[(size_t)r * full + i];
        float u = gu[(size_t)r * full + half + i];
        h[(size_t)r * half + i] = silu_f(g) * u;
    }
}

// out[m,:] += sum of this token's 4 per-pair outputs (fixed order -> deterministic)
__global__ void combine_kernel(float* __restrict__ out) {
    int m = blockIdx.x;
    int s0 = g_slot_of[m * TOPK + 0];
    int s1 = g_slot_of[m * TOPK + 1];
    int s2 = g_slot_of[m * TOPK + 2];
    int s3 = g_slot_of[m * TOPK + 3];
    for (int hcol = threadIdx.x; hcol < H; hcol += blockDim.x) {
        float v = out[(size_t)m * H + hcol];
        v += g_y[(size_t)s0 * H + hcol];
        v += g_y[(size_t)s1 * H + hcol];
        v += g_y[(size_t)s2 * H + hcol];
        v += g_y[(size_t)s3 * H + hcol];
        out[(size_t)m * H + hcol] = v;
    }
}

// ---------------- SGEMM: C[M,N] = A[M,K] @ B[N,K]^T ----------------
// 128x128 tile, BK=16, 256 threads, 8x8 per thread.
#define BM 128
#define BN 128
#define BK 16
#define SPAD 4

template<bool ROWSCALE>
__global__ void __launch_bounds__(256, 2) sgemm_dense(
    const float* __restrict__ A, const float* __restrict__ B, float* __restrict__ C,
    int Ntot, int K, const float* __restrict__ rscale) {
    __shared__ float As[BK][BM + SPAD];
    __shared__ float Bs[BK][BN + SPAD];
    int n0 = blockIdx.x * BN, m0 = blockIdx.y * BM;
    int tid = threadIdx.x;
    int tm = tid >> 4, tn = tid & 15;
    float c[8][8] = {};

    for (int k0 = 0; k0 < K; k0 += BK) {
        #pragma unroll
        for (int t = 0; t < 2; t++) {
            int f = tid + t * 256;
            int r = f >> 2, kq = (f & 3) << 2;
            float4 va = *reinterpret_cast<const float4*>(A + (size_t)(m0 + r) * K + k0 + kq);
            As[kq + 0][r] = va.x; As[kq + 1][r] = va.y; As[kq + 2][r] = va.z; As[kq + 3][r] = va.w;
            float4 vb = *reinterpret_cast<const float4*>(B + (size_t)(n0 + r) * K + k0 + kq);
            Bs[kq + 0][r] = vb.x; Bs[kq + 1][r] = vb.y; Bs[kq + 2][r] = vb.z; Bs[kq + 3][r] = vb.w;
        }
        __syncthreads();
        #pragma unroll
        for (int kk = 0; kk < BK; kk++) {
            float a[8], b[8];
            #pragma unroll
            for (int i = 0; i < 8; i++) a[i] = As[kk][tm * 8 + i];
            #pragma unroll
            for (int j = 0; j < 8; j++) b[j] = Bs[kk][tn * 8 + j];
            #pragma unroll
            for (int i = 0; i < 8; i++)
                #pragma unroll
                for (int j = 0; j < 8; j++)
                    c[i][j] += a[i] * b[j];
        }
        __syncthreads();
    }
    #pragma unroll
    for (int i = 0; i < 8; i++) {
        int gm = m0 + tm * 8 + i;
        float s = ROWSCALE ? rscale[gm] : 1.f;
        #pragma unroll
        for (int j = 0; j < 8; j += 4) {
            float4 v = make_float4(c[i][j] * s, c[i][j + 1] * s, c[i][j + 2] * s, c[i][j + 3] * s);
            *reinterpret_cast<float4*>(C + (size_t)gm * Ntot + n0 + tn * 8 + j) = v;
        }
    }
}

// Routed grouped GEMM: per expert e, rows = slots [off[e], off[e]+cnt[e]).
// GATHER: A row comes from x via g_slot_token; else A row = slot directly.
// SCALE: multiply output row by g_slot_w[slot].
template<bool GATHER, bool SCALE>
__global__ void __launch_bounds__(256, 2) sgemm_routed(
    const float* __restrict__ A, int lda,
    const float* __restrict__ Bbase, size_t strideB,
    float* __restrict__ C, int Ntot, int K) {
    int e = blockIdx.z;
    int cnt = g_cnt[e];
    int mt = blockIdx.y;
    if (mt * BM >= cnt) return;
    int off = g_off[e];
    const float* B = Bbase + (size_t)e * strideB;

    __shared__ float As[BK][BM + SPAD];
    __shared__ float Bs[BK][BN + SPAD];
    int n0 = blockIdx.x * BN;
    int tid = threadIdx.x;
    int tm = tid >> 4, tn = tid & 15;

    // Precompute the 2 A-rows this thread loads each k-iteration.
    int r0 = tid >> 2, r1 = (tid + 256) >> 2;
    int l0 = mt * BM + r0, l1 = mt * BM + r1;
    long arow0 = -1, arow1 = -1;
    if (l0 < cnt) arow0 = GATHER ? (long)g_slot_token[off + l0] : (long)(off + l0);
    if (l1 < cnt) arow1 = GATHER ? (long)g_slot_token[off + l1] : (long)(off + l1);

    float c[8][8] = {};
    int kq0 = (tid & 3) << 2;

    for (int k0 = 0; k0 < K; k0 += BK) {
        {
            float4 va = (arow0 >= 0)
                ? *reinterpret_cast<const float4*>(A + (size_t)arow0 * lda + k0 + kq0)
                : make_float4(0.f, 0.f, 0.f, 0.f);
            As[kq0 + 0][r0] = va.x; As[kq0 + 1][r0] = va.y; As[kq0 + 2][r0] = va.z; As[kq0 + 3][r0] = va.w;
            float4 vb = *reinterpret_cast<const float4*>(B + (size_t)(n0 + r0) * K + k0 + kq0);
            Bs[kq0 + 0][r0] = vb.x; Bs[kq0 + 1][r0] = vb.y; Bs[kq0 + 2][r0] = vb.z; Bs[kq0 + 3][r0] = vb.w;
        }
        {
            float4 va = (arow1 >= 0)
                ? *reinterpret_cast<const float4*>(A + (size_t)arow1 * lda + k0 + kq0)
                : make_float4(0.f, 0.f, 0.f, 0.f);
            As[kq0 + 0][r1] = va.x; As[kq0 + 1][r1] = va.y; As[kq0 + 2][r1] = va.z; As[kq0 + 3][r1] = va.w;
            float4 vb = *reinterpret_cast<const float4*>(B + (size_t)(n0 + r1) * K + k0 + kq0);
            Bs[kq0 + 0][r1] = vb.x; Bs[kq0 + 1][r1] = vb.y; Bs[kq0 + 2][r1] = vb.z; Bs[kq0 + 3][r1] = vb.w;
        }
        __syncthreads();
        #pragma unroll
        for (int kk = 0; kk < BK; kk++) {
            float a[8], b[8];
            #pragma unroll
            for (int i = 0; i < 8; i++) a[i] = As[kk][tm * 8 + i];
            #pragma unroll
            for (int j = 0; j < 8; j++) b[j] = Bs[kk][tn * 8 + j];
            #pragma unroll
            for (int i = 0; i < 8; i++)
                #pragma unroll
                for (int j = 0; j < 8; j++)
                    c[i][j] += a[i] * b[j];
        }
        __syncthreads();
    }

    #pragma unroll
    for (int i = 0; i < 8; i++) {
        int l = mt * BM + tm * 8 + i;
        if (l >= cnt) continue;
        int slot = off + l;
        float s = SCALE ? g_slot_w[slot] : 1.f;
        #pragma unroll
        for (int j = 0; j < 8; j += 4) {
            float4 v = make_float4(c[i][j] * s, c[i][j + 1] * s, c[i][j + 2] * s, c[i][j + 3] * s);
            *reinterpret_cast<float4*>(C + (size_t)slot * Ntot + n0 + tn * 8 + j) = v;
        }
    }
}

// ---------------- launch ----------------
extern "C" void kernel_launch(void* const* d_in, const int* in_sizes, int n_in,
                              void* d_out, int out_size) {
    const float* x      = (const float*)d_in[0];   // [M, H]
    const float* gate_w = (const float*)d_in[1];   // [E, H]
    const float* sgw    = (const float*)d_in[2];   // [1, H]
    const float* w13    = (const float*)d_in[3];   // [E, 2I, H]
    const float* w2     = (const float*)d_in[4];   // [E, H, I]
    const float* segu   = (const float*)d_in[5];   // [2*ISH, H]
    const float* sedw   = (const float*)d_in[6];   // [H, ISH]
    float* out = (float*)d_out;

    int M = in_sizes[0] / H;                       // 1024

    float *gu_p, *hsh_p, *gur_p, *hr_p, *y_p, *sig_p;
    cudaGetSymbolAddress((void**)&gu_p,  g_gu);
    cudaGetSymbolAddress((void**)&hsh_p, g_hsh);
    cudaGetSymbolAddress((void**)&gur_p, g_gur);
    cudaGetSymbolAddress((void**)&hr_p,  g_hr);
    cudaGetSymbolAddress((void**)&y_p,   g_y);
    cudaGetSymbolAddress((void**)&sig_p, g_sig);

    // routing pipeline
    zero_counts_kernel<<<1, 64>>>();
    router_kernel<<<M, 256>>>(x, gate_w, sgw);
    scan_kernel<<<1, 32>>>();
    fill_kernel<<<(M + 255) / 256, 256>>>(M);

    // shared expert
    sgemm_dense<false><<<dim3(ISH2 / BN, M / BM), 256>>>(x, segu, gu_p, ISH2, H, nullptr);
    silu_mul_kernel<<<1024, 256>>>(gu_p, hsh_p, M, ISH, ISH2);
    sgemm_dense<true><<<dim3(H / BN, M / BM), 256>>>(hsh_p, sedw, out, H, ISH, sig_p);

    // routed experts (grouped GEMMs over gathered tokens)
    int mtiles = (M + BM - 1) / BM;   // worst case: all tokens on one expert
    sgemm_routed<true, false><<<dim3(I2 / BN, mtiles, E), 256>>>(
        x, H, w13, (size_t)I2 * H, gur_p, I2, H);
    silu_mul_kernel<<<1024, 256>>>(gur_p, hr_p, M * TOPK, II, I2);
    sgemm_routed<false, true><<<dim3(H / BN, mtiles, E), 256>>>(
        hr_p, II, w2, (size_t)H * II, y_p, H, II);

    // deterministic per-token combine
    combine_kernel<<<M, 256>>>(out);
}

// round 3
// speedup vs baseline: 2.2988x; 2.2988x over previous
#include <cuda_runtime.h>
#include <math.h>
#include <stdint.h>

// ================= problem constants =================
#define H     2048
#define E     60
#define II    1408
#define I2    2816
#define ISH   5632
#define ISH2  11264
#define TOPK  4
#define MAXM  1024
#define MAXSLOTS (MAXM*TOPK)

// ================= device scratch =================
static __device__ float g_gu  [MAXM * ISH2];
static __device__ float g_hsh [MAXM * ISH];
static __device__ float g_gur [MAXSLOTS * I2];
static __device__ float g_hr  [MAXSLOTS * II];
static __device__ float g_y   [MAXSLOTS * H];
static __device__ float g_sig [MAXM];
static __device__ int   g_cnt [E];
static __device__ int   g_off [E];
static __device__ int   g_cur [E];
static __device__ int   g_slot_token[MAXSLOTS];
static __device__ float g_slot_w    [MAXSLOTS];
static __device__ int   g_slot_of   [MAXM * TOPK];
static __device__ int   g_tk_e      [MAXM * TOPK];
static __device__ float g_tk_w      [MAXM * TOPK];

// ================= small kernels =================
__global__ void zero_counts_kernel() {
    int t = threadIdx.x;
    if (t < E) g_cnt[t] = 0;
}

__global__ void router_kernel(const float* __restrict__ x,
                              const float* __restrict__ gate_w,
                              const float* __restrict__ sgw) {
    __shared__ float xs[H];
    __shared__ float logits[E + 1];
    int m = blockIdx.x;
    const float* xr = x + (size_t)m * H;
    for (int i = threadIdx.x; i < H; i += blockDim.x) xs[i] = xr[i];
    __syncthreads();

    int wid = threadIdx.x >> 5, lane = threadIdx.x & 31;
    for (int e = wid; e <= E; e += 8) {
        const float* wr = (e < E) ? (gate_w + (size_t)e * H) : sgw;
        float acc = 0.f;
        for (int k = lane; k < H; k += 32) acc += xs[k] * wr[k];
        #pragma unroll
        for (int o = 16; o; o >>= 1) acc += __shfl_xor_sync(0xffffffffu, acc, o);
        if (lane == 0) logits[e] = acc;
    }
    __syncthreads();

    if (threadIdx.x == 0) {
        g_sig[m] = 1.f / (1.f + expf(-logits[E]));
        float mx = -1e30f;
        for (int e = 0; e < E; e++) mx = fmaxf(mx, logits[e]);
        float sum = 0.f;
        for (int e = 0; e < E; e++) { float p = expf(logits[e] - mx); logits[e] = p; sum += p; }
        float inv = 1.f / sum;
        for (int k = 0; k < TOPK; k++) {
            int best = 0; float bv = -1.f;
            for (int e = 0; e < E; e++) { float v = logits[e]; if (v > bv) { bv = v; best = e; } }
            logits[best] = -2.f;
            g_tk_e[m * TOPK + k] = best;
            g_tk_w[m * TOPK + k] = bv * inv;
            atomicAdd(&g_cnt[best], 1);
        }
    }
}

__global__ void scan_kernel() {
    if (threadIdx.x == 0) {
        int s = 0;
        for (int e = 0; e < E; e++) { g_off[e] = s; s += g_cnt[e]; g_cur[e] = 0; }
    }
}

__global__ void fill_kernel(int M) {
    int m = blockIdx.x * blockDim.x + threadIdx.x;
    if (m >= M) return;
    for (int k = 0; k < TOPK; k++) {
        int e = g_tk_e[m * TOPK + k];
        int pos = atomicAdd(&g_cur[e], 1);
        int slot = g_off[e] + pos;
        g_slot_token[slot] = m;
        g_slot_w[slot] = g_tk_w[m * TOPK + k];
        g_slot_of[m * TOPK + k] = slot;
    }
}

__device__ __forceinline__ float silu_f(float v) { return v / (1.f + expf(-v)); }

__global__ void silu_mul_kernel(const float* __restrict__ gu, float* __restrict__ h,
                                int rows, int half, int full) {
    int total = rows * half;
    for (int idx = blockIdx.x * blockDim.x + threadIdx.x; idx < total;
         idx += gridDim.x * blockDim.x) {
        int r = idx / half, i = idx - r * half;
        float g = gu[(size_t)r * full + i];
        float u = gu[(size_t)r * full + half + i];
        h[(size_t)r * half + i] = silu_f(g) * u;
    }
}

__global__ void combine_kernel(float* __restrict__ out) {
    int m = blockIdx.x;
    int s0 = g_slot_of[m * TOPK + 0];
    int s1 = g_slot_of[m * TOPK + 1];
    int s2 = g_slot_of[m * TOPK + 2];
    int s3 = g_slot_of[m * TOPK + 3];
    for (int hcol = threadIdx.x; hcol < H; hcol += blockDim.x) {
        float v = out[(size_t)m * H + hcol];
        v += g_y[(size_t)s0 * H + hcol];
        v += g_y[(size_t)s1 * H + hcol];
        v += g_y[(size_t)s2 * H + hcol];
        v += g_y[(size_t)s3 * H + hcol];
        out[(size_t)m * H + hcol] = v;
    }
}

// ================= mma.sync GEMM (base PTX, sm_80+ features only) =================
// C[M,N] = A[M,K] @ B[N,K]^T in fp32 via bf16 hi/lo 3-pass split.
// Tile 128x128, KC=32 fp32/chunk, 512 threads (16 warps, 4x4), warp tile 32x32.
// SMEM per stage: A_hi, A_lo, B_hi, B_lo  each [128 rows][40 halves] (80B rows,
// conflict-free for ldmatrix since 80B stride spreads rows over distinct banks).
#define KC       32
#define ROWB     80                 // bytes per smem row (32 halves + 8 pad)
#define SUBT     (128 * ROWB)       // 10240 B
#define AH_OFF   0
#define AL_OFF   (1 * SUBT)
#define BH_OFF   (2 * SUBT)
#define BL_OFF   (3 * SUBT)
#define STAGE    (4 * SUBT)         // 40960 B
#define GEMM_SMEM (2 * STAGE)       // 81920 B

__device__ __forceinline__ uint32_t smem_u32(const void* p) {
    uint32_t a;
    asm("{ .reg .u64 t; cvta.to.shared.u64 t, %1; cvt.u32.u64 %0, t; }" : "=r"(a) : "l"(p));
    return a;
}

#define LDSM4(r, addr) \
    asm volatile("ldmatrix.sync.aligned.m8n8.x4.shared.b16 {%0,%1,%2,%3}, [%4];" \
        : "=r"((r)[0]), "=r"((r)[1]), "=r"((r)[2]), "=r"((r)[3]) : "r"(addr))

#define MMA_BF16(c, a, b0, b1) \
    asm volatile("mma.sync.aligned.m16n8k16.row.col.f32.bf16.bf16.f32 " \
        "{%0,%1,%2,%3}, {%4,%5,%6,%7}, {%8,%9}, {%0,%1,%2,%3};" \
        : "+f"((c)[0]), "+f"((c)[1]), "+f"((c)[2]), "+f"((c)[3]) \
        : "r"((a)[0]), "r"((a)[1]), "r"((a)[2]), "r"((a)[3]), "r"(b0), "r"(b1))

// 8 fp32 -> 8 bf16 hi + 8 bf16 lo (memory order preserved: low half of each
// packed u32 is the lower-index element).
__device__ __forceinline__ void cvt8(float4 v0, float4 v1, uint4& hi, uint4& lo) {
    uint32_t h01, h23, h45, h67;
    asm("cvt.rn.bf16x2.f32 %0, %1, %2;" : "=r"(h01) : "f"(v0.y), "f"(v0.x));
    asm("cvt.rn.bf16x2.f32 %0, %1, %2;" : "=r"(h23) : "f"(v0.w), "f"(v0.z));
    asm("cvt.rn.bf16x2.f32 %0, %1, %2;" : "=r"(h45) : "f"(v1.y), "f"(v1.x));
    asm("cvt.rn.bf16x2.f32 %0, %1, %2;" : "=r"(h67) : "f"(v1.w), "f"(v1.z));
    float fx0 = __uint_as_float(h01 << 16), fy0 = __uint_as_float(h01 & 0xffff0000u);
    float fz0 = __uint_as_float(h23 << 16), fw0 = __uint_as_float(h23 & 0xffff0000u);
    float fx1 = __uint_as_float(h45 << 16), fy1 = __uint_as_float(h45 & 0xffff0000u);
    float fz1 = __uint_as_float(h67 << 16), fw1 = __uint_as_float(h67 & 0xffff0000u);
    uint32_t l01, l23, l45, l67;
    asm("cvt.rn.bf16x2.f32 %0, %1, %2;" : "=r"(l01) : "f"(v0.y - fy0), "f"(v0.x - fx0));
    asm("cvt.rn.bf16x2.f32 %0, %1, %2;" : "=r"(l23) : "f"(v0.w - fw0), "f"(v0.z - fz0));
    asm("cvt.rn.bf16x2.f32 %0, %1, %2;" : "=r"(l45) : "f"(v1.y - fy1), "f"(v1.x - fx1));
    asm("cvt.rn.bf16x2.f32 %0, %1, %2;" : "=r"(l67) : "f"(v1.w - fw1), "f"(v1.z - fz1));
    hi = make_uint4(h01, h23, h45, h67);
    lo = make_uint4(l01, l23, l45, l67);
}

// GATHER: A row via g_slot_token[off+l]; ROUTED: grid.z = expert.
// SCALEMODE: 0 none, 1 g_slot_w[slot], 2 rscale[row].
template<int GATHER, int ROUTED, int SCALEMODE>
__global__ void __launch_bounds__(512, 1) mma_gemm(
    const float* __restrict__ A, int lda,
    const float* __restrict__ Bbase, size_t strideB,
    float* __restrict__ C, int Ntot, int K,
    const float* __restrict__ rscale)
{
    extern __shared__ char smem[];
    int cnt = 0x3fffffff, off = 0, m0 = blockIdx.y * 128;
    const float* Bp = Bbase;
    if (ROUTED) {
        int e = blockIdx.z;
        cnt = g_cnt[e];
        if (m0 >= cnt) return;
        off = g_off[e];
        Bp += (size_t)e * strideB;
    }
    int n0 = blockIdx.x * 128;
    int tid = threadIdx.x;

    // ---- load/convert mapping: thread t -> row r = t>>2, fp32 cols cq..cq+7 ----
    int r = tid >> 2;
    int cq = (tid & 3) << 3;
    long arow;
    if (!ROUTED) arow = m0 + r;
    else {
        int l = m0 + r;
        arow = (l < cnt) ? (GATHER ? (long)g_slot_token[off + l] : (long)(off + l)) : -1;
    }
    bool av = (arow >= 0);
    const float* apf = A + (size_t)(av ? arow : 0) * lda + cq;
    const float* bpf = Bp + (size_t)(n0 + r) * K + cq;
    uint32_t sw = (uint32_t)(r * ROWB + cq * 2);   // 16B-aligned smem byte offset

    uint32_t sm0 = smem_u32(smem);

    // ---- ldmatrix per-thread bases ----
    int lane = tid & 31, wid = tid >> 5;
    int wm = wid & 3, wn = wid >> 2;               // warp grid 4(m) x 4(n)
    uint32_t lmoff = (uint32_t)((lane & 15) * ROWB + (lane >> 4) * 16);
    uint32_t aBase = sm0 + AH_OFF + (uint32_t)(wm * 32 * ROWB) + lmoff;
    uint32_t bBase = sm0 + BH_OFF + (uint32_t)(wn * 32 * ROWB) + lmoff;

    float c[2][4][4];
    #pragma unroll
    for (int i = 0; i < 2; i++)
        #pragma unroll
        for (int j = 0; j < 4; j++)
            #pragma unroll
            for (int q = 0; q < 4; q++) c[i][j][q] = 0.f;

    int KT = K / KC;
    const float4 z4 = make_float4(0.f, 0.f, 0.f, 0.f);
    float4 ra0, ra1, rb0, rb1;
    ra0 = av ? *(const float4*)(apf + 0) : z4;
    ra1 = av ? *(const float4*)(apf + 4) : z4;
    rb0 = *(const float4*)(bpf + 0);
    rb1 = *(const float4*)(bpf + 4);

    for (int kt = 0; kt < KT; kt++) {
        uint32_t st = (kt & 1) * STAGE;
        char* sb = smem + st;
        {
            uint4 hi, lo;
            cvt8(ra0, ra1, hi, lo);
            *(uint4*)(sb + AH_OFF + sw) = hi;
            *(uint4*)(sb + AL_OFF + sw) = lo;
            cvt8(rb0, rb1, hi, lo);
            *(uint4*)(sb + BH_OFF + sw) = hi;
            *(uint4*)(sb + BL_OFF + sw) = lo;
        }
        __syncthreads();

        if (kt + 1 < KT) {
            const float* ap = apf + (kt + 1) * KC;
            const float* bp = bpf + (kt + 1) * KC;
            ra0 = av ? *(const float4*)(ap + 0) : z4;
            ra1 = av ? *(const float4*)(ap + 4) : z4;
            rb0 = *(const float4*)(bp + 0);
            rb1 = *(const float4*)(bp + 4);
        }

        uint32_t ab = aBase + st, bb = bBase + st;
        #pragma unroll
        for (int kk = 0; kk < 2; kk++) {
            uint32_t ah[2][4], al[2][4], bh[2][4], bl[2][4];
            #pragma unroll
            for (int mi = 0; mi < 2; mi++) {
                uint32_t ad = ab + mi * (16 * ROWB) + kk * 32;
                LDSM4(ah[mi], ad);
                LDSM4(al[mi], ad + (AL_OFF - AH_OFF));
            }
            #pragma unroll
            for (int j = 0; j < 2; j++) {
                uint32_t bd = bb + j * (16 * ROWB) + kk * 32;
                LDSM4(bh[j], bd);
                LDSM4(bl[j], bd + (BL_OFF - BH_OFF));
            }
            #pragma unroll
            for (int mi = 0; mi < 2; mi++) {
                #pragma unroll
                for (int ns = 0; ns < 4; ns++) {
                    int j = ns >> 1, sel = ns & 1;
                    MMA_BF16(c[mi][ns], ah[mi], bh[j][sel], bh[j][sel + 2]);
                    MMA_BF16(c[mi][ns], ah[mi], bl[j][sel], bl[j][sel + 2]);
                    MMA_BF16(c[mi][ns], al[mi], bh[j][sel], bh[j][sel + 2]);
                }
            }
        }
        __syncthreads();
    }

    // ---- epilogue ----
    #pragma unroll
    for (int mi = 0; mi < 2; mi++) {
        int lr0 = m0 + wm * 32 + mi * 16 + (lane >> 2);
        int lr1 = lr0 + 8;
        #pragma unroll
        for (int half = 0; half < 2; half++) {
            int lr = half ? lr1 : lr0;
            if (ROUTED && (lr - m0) + m0 >= cnt + m0) {}   // (placate compiler)
            bool valid = !ROUTED || (lr < cnt);
            if (!valid) continue;
            int orow = ROUTED ? (off + lr) : lr;
            float s = 1.f;
            if (SCALEMODE == 1) s = g_slot_w[off + lr];
            if (SCALEMODE == 2) s = rscale[lr];
            float* cp = C + (size_t)orow * Ntot + n0 + wn * 32 + (lane & 3) * 2;
            #pragma unroll
            for (int ns = 0; ns < 4; ns++) {
                float2 v = make_float2(c[mi][ns][half * 2 + 0] * s,
                                       c[mi][ns][half * 2 + 1] * s);
                *(float2*)(cp + ns * 8) = v;
            }
        }
    }
}

// ================= launch =================
extern "C" void kernel_launch(void* const* d_in, const int* in_sizes, int n_in,
                              void* d_out, int out_size) {
    const float* x      = (const float*)d_in[0];
    const float* gate_w = (const float*)d_in[1];
    const float* sgw    = (const float*)d_in[2];
    const float* w13    = (const float*)d_in[3];
    const float* w2     = (const float*)d_in[4];
    const float* segu   = (const float*)d_in[5];
    const float* sedw   = (const float*)d_in[6];
    float* out = (float*)d_out;

    int M = in_sizes[0] / H;   // 1024

    float *gu_p, *hsh_p, *gur_p, *hr_p, *y_p, *sig_p;
    cudaGetSymbolAddress((void**)&gu_p,  g_gu);
    cudaGetSymbolAddress((void**)&hsh_p, g_hsh);
    cudaGetSymbolAddress((void**)&gur_p, g_gur);
    cudaGetSymbolAddress((void**)&hr_p,  g_hr);
    cudaGetSymbolAddress((void**)&y_p,   g_y);
    cudaGetSymbolAddress((void**)&sig_p, g_sig);

    cudaFuncSetAttribute(mma_gemm<0,0,0>, cudaFuncAttributeMaxDynamicSharedMemorySize, GEMM_SMEM);
    cudaFuncSetAttribute(mma_gemm<0,0,2>, cudaFuncAttributeMaxDynamicSharedMemorySize, GEMM_SMEM);
    cudaFuncSetAttribute(mma_gemm<1,1,0>, cudaFuncAttributeMaxDynamicSharedMemorySize, GEMM_SMEM);
    cudaFuncSetAttribute(mma_gemm<0,1,1>, cudaFuncAttributeMaxDynamicSharedMemorySize, GEMM_SMEM);

    // routing pipeline
    zero_counts_kernel<<<1, 64>>>();
    router_kernel<<<M, 256>>>(x, gate_w, sgw);
    scan_kernel<<<1, 32>>>();
    fill_kernel<<<(M + 255) / 256, 256>>>(M);

    // shared expert
    mma_gemm<0,0,0><<<dim3(ISH2 / 128, M / 128), 512, GEMM_SMEM>>>(
        x, H, segu, 0, gu_p, ISH2, H, nullptr);
    silu_mul_kernel<<<1024, 256>>>(gu_p, hsh_p, M, ISH, ISH2);
    mma_gemm<0,0,2><<<dim3(H / 128, M / 128), 512, GEMM_SMEM>>>(
        hsh_p, ISH, sedw, 0, out, H, ISH, sig_p);

    // routed experts
    int mtiles = M / 128;   // worst case: all tokens on one expert
    mma_gemm<1,1,0><<<dim3(I2 / 128, mtiles, E), 512, GEMM_SMEM>>>(
        x, H, w13, (size_t)I2 * H, gur_p, I2, H, nullptr);
    silu_mul_kernel<<<1024, 256>>>(gur_p, hr_p, M * TOPK, II, I2);
    mma_gemm<0,1,1><<<dim3(H / 128, mtiles, E), 512, GEMM_SMEM>>>(
        hr_p, II, w2, (size_t)H * II, y_p, H, II, nullptr);

    // deterministic per-token combine
    combine_kernel<<<M, 256>>>(out);
}

// round 4
// speedup vs baseline: 2.4830x; 1.0801x over previous
#include <cuda_runtime.h>
#include <math.h>
#include <stdint.h>

// ================= problem constants =================
#define H     2048
#define E     60
#define II    1408
#define I2    2816
#define ISH   5632
#define ISH2  11264
#define TOPK  4
#define MAXM  1024
#define MAXSLOTS (MAXM*TOPK)

// ================= device scratch =================
static __device__ float g_gu  [MAXM * ISH2];
static __device__ float g_hsh [MAXM * ISH];
static __device__ float g_gur [MAXSLOTS * I2];
static __device__ float g_hr  [MAXSLOTS * II];
static __device__ float g_y   [MAXSLOTS * H];
static __device__ float g_sig [MAXM];
static __device__ int   g_cnt [E];
static __device__ int   g_off [E];
static __device__ int   g_cur [E];
static __device__ int   g_slot_token[MAXSLOTS];
static __device__ float g_slot_w    [MAXSLOTS];
static __device__ int   g_slot_of   [MAXM * TOPK];
static __device__ int   g_tk_e      [MAXM * TOPK];
static __device__ float g_tk_w      [MAXM * TOPK];

// ================= small kernels =================
__global__ void zero_counts_kernel() {
    int t = threadIdx.x;
    if (t < E) g_cnt[t] = 0;
}

__global__ void router_kernel(const float* __restrict__ x,
                              const float* __restrict__ gate_w,
                              const float* __restrict__ sgw) {
    __shared__ float xs[H];
    __shared__ float logits[E + 1];
    int m = blockIdx.x;
    const float* xr = x + (size_t)m * H;
    for (int i = threadIdx.x; i < H; i += blockDim.x) xs[i] = xr[i];
    __syncthreads();

    int wid = threadIdx.x >> 5, lane = threadIdx.x & 31;
    for (int e = wid; e <= E; e += 8) {
        const float* wr = (e < E) ? (gate_w + (size_t)e * H) : sgw;
        float acc = 0.f;
        for (int k = lane; k < H; k += 32) acc += xs[k] * wr[k];
        #pragma unroll
        for (int o = 16; o; o >>= 1) acc += __shfl_xor_sync(0xffffffffu, acc, o);
        if (lane == 0) logits[e] = acc;
    }
    __syncthreads();

    if (threadIdx.x == 0) {
        g_sig[m] = 1.f / (1.f + expf(-logits[E]));
        float mx = -1e30f;
        for (int e = 0; e < E; e++) mx = fmaxf(mx, logits[e]);
        float sum = 0.f;
        for (int e = 0; e < E; e++) { float p = expf(logits[e] - mx); logits[e] = p; sum += p; }
        float inv = 1.f / sum;
        for (int k = 0; k < TOPK; k++) {
            int best = 0; float bv = -1.f;
            for (int e = 0; e < E; e++) { float v = logits[e]; if (v > bv) { bv = v; best = e; } }
            logits[best] = -2.f;
            g_tk_e[m * TOPK + k] = best;
            g_tk_w[m * TOPK + k] = bv * inv;
            atomicAdd(&g_cnt[best], 1);
        }
    }
}

__global__ void scan_kernel() {
    if (threadIdx.x == 0) {
        int s = 0;
        for (int e = 0; e < E; e++) { g_off[e] = s; s += g_cnt[e]; g_cur[e] = 0; }
    }
}

__global__ void fill_kernel(int M) {
    int m = blockIdx.x * blockDim.x + threadIdx.x;
    if (m >= M) return;
    for (int k = 0; k < TOPK; k++) {
        int e = g_tk_e[m * TOPK + k];
        int pos = atomicAdd(&g_cur[e], 1);
        int slot = g_off[e] + pos;
        g_slot_token[slot] = m;
        g_slot_w[slot] = g_tk_w[m * TOPK + k];
        g_slot_of[m * TOPK + k] = slot;
    }
}

__device__ __forceinline__ float silu_f(float v) { return v / (1.f + expf(-v)); }

__global__ void silu_mul_kernel(const float* __restrict__ gu, float* __restrict__ h,
                                int rows, int half, int full) {
    int total = rows * half;
    for (int idx = blockIdx.x * blockDim.x + threadIdx.x; idx < total;
         idx += gridDim.x * blockDim.x) {
        int r = idx / half, i = idx - r * half;
        float g = gu[(size_t)r * full + i];
        float u = gu[(size_t)r * full + half + i];
        h[(size_t)r * half + i] = silu_f(g) * u;
    }
}

__global__ void combine_kernel(float* __restrict__ out) {
    int m = blockIdx.x;
    int s0 = g_slot_of[m * TOPK + 0];
    int s1 = g_slot_of[m * TOPK + 1];
    int s2 = g_slot_of[m * TOPK + 2];
    int s3 = g_slot_of[m * TOPK + 3];
    for (int hcol = threadIdx.x; hcol < H; hcol += blockDim.x) {
        float v = out[(size_t)m * H + hcol];
        v += g_y[(size_t)s0 * H + hcol];
        v += g_y[(size_t)s1 * H + hcol];
        v += g_y[(size_t)s2 * H + hcol];
        v += g_y[(size_t)s3 * H + hcol];
        out[(size_t)m * H + hcol] = v;
    }
}

// ================= mma.sync GEMM (base PTX, sm_80+ features only) =================
// C[M,N] = A[M,K] @ B[N,K]^T in fp32 via bf16 hi/lo 3-pass split.
// Tile 128x128, KC=32 fp32/chunk, 512 threads (16 warps, 4x4), warp tile 32x32.
// 2-stage SMEM ring, ONE __syncthreads per chunk (store(k+2) to stage s only
// happens after sync(k+1), which all warps pass only after mma(k) read stage s).
#define KC       32
#define ROWB     80                 // bytes per smem row (32 halves + 8 pad)
#define SUBT     (128 * ROWB)       // 10240 B
#define AH_OFF   0
#define AL_OFF   (1 * SUBT)
#define BH_OFF   (2 * SUBT)
#define BL_OFF   (3 * SUBT)
#define STAGE    (4 * SUBT)         // 40960 B
#define GEMM_SMEM (2 * STAGE)       // 81920 B

__device__ __forceinline__ uint32_t smem_u32(const void* p) {
    uint32_t a;
    asm("{ .reg .u64 t; cvta.to.shared.u64 t, %1; cvt.u32.u64 %0, t; }" : "=r"(a) : "l"(p));
    return a;
}

#define LDSM4(r, addr) \
    asm volatile("ldmatrix.sync.aligned.m8n8.x4.shared.b16 {%0,%1,%2,%3}, [%4];" \
        : "=r"((r)[0]), "=r"((r)[1]), "=r"((r)[2]), "=r"((r)[3]) : "r"(addr))

#define MMA_BF16(c, a, b0, b1) \
    asm volatile("mma.sync.aligned.m16n8k16.row.col.f32.bf16.bf16.f32 " \
        "{%0,%1,%2,%3}, {%4,%5,%6,%7}, {%8,%9}, {%0,%1,%2,%3};" \
        : "+f"((c)[0]), "+f"((c)[1]), "+f"((c)[2]), "+f"((c)[3]) \
        : "r"((a)[0]), "r"((a)[1]), "r"((a)[2]), "r"((a)[3]), "r"(b0), "r"(b1))

// 8 fp32 -> 8 bf16 hi + 8 bf16 lo (memory order preserved).
__device__ __forceinline__ void cvt8(float4 v0, float4 v1, uint4& hi, uint4& lo) {
    uint32_t h01, h23, h45, h67;
    asm("cvt.rn.bf16x2.f32 %0, %1, %2;" : "=r"(h01) : "f"(v0.y), "f"(v0.x));
    asm("cvt.rn.bf16x2.f32 %0, %1, %2;" : "=r"(h23) : "f"(v0.w), "f"(v0.z));
    asm("cvt.rn.bf16x2.f32 %0, %1, %2;" : "=r"(h45) : "f"(v1.y), "f"(v1.x));
    asm("cvt.rn.bf16x2.f32 %0, %1, %2;" : "=r"(h67) : "f"(v1.w), "f"(v1.z));
    float fx0 = __uint_as_float(h01 << 16), fy0 = __uint_as_float(h01 & 0xffff0000u);
    float fz0 = __uint_as_float(h23 << 16), fw0 = __uint_as_float(h23 & 0xffff0000u);
    float fx1 = __uint_as_float(h45 << 16), fy1 = __uint_as_float(h45 & 0xffff0000u);
    float fz1 = __uint_as_float(h67 << 16), fw1 = __uint_as_float(h67 & 0xffff0000u);
    uint32_t l01, l23, l45, l67;
    asm("cvt.rn.bf16x2.f32 %0, %1, %2;" : "=r"(l01) : "f"(v0.y - fy0), "f"(v0.x - fx0));
    asm("cvt.rn.bf16x2.f32 %0, %1, %2;" : "=r"(l23) : "f"(v0.w - fw0), "f"(v0.z - fz0));
    asm("cvt.rn.bf16x2.f32 %0, %1, %2;" : "=r"(l45) : "f"(v1.y - fy1), "f"(v1.x - fx1));
    asm("cvt.rn.bf16x2.f32 %0, %1, %2;" : "=r"(l67) : "f"(v1.w - fw1), "f"(v1.z - fz1));
    hi = make_uint4(h01, h23, h45, h67);
    lo = make_uint4(l01, l23, l45, l67);
}

// GATHER: A row via g_slot_token[off+l]; ROUTED: grid.z = expert.
// SCALEMODE: 0 none, 1 g_slot_w[slot], 2 rscale[row].
template<int GATHER, int ROUTED, int SCALEMODE>
__global__ void __launch_bounds__(512, 1) mma_gemm(
    const float* __restrict__ A, int lda,
    const float* __restrict__ Bbase, size_t strideB,
    float* __restrict__ C, int Ntot, int K,
    const float* __restrict__ rscale)
{
    extern __shared__ char smem[];
    int cnt = 0x3fffffff, off = 0, m0 = blockIdx.y * 128;
    const float* Bp = Bbase;
    if (ROUTED) {
        int e = blockIdx.z;
        cnt = g_cnt[e];
        if (m0 >= cnt) return;
        off = g_off[e];
        Bp += (size_t)e * strideB;
    }
    int n0 = blockIdx.x * 128;
    int tid = threadIdx.x;

    // ---- load/convert mapping: thread t -> row r = t>>2, fp32 cols cq..cq+7 ----
    int r = tid >> 2;
    int cq = (tid & 3) << 3;
    long arow;
    if (!ROUTED) arow = m0 + r;
    else {
        int l = m0 + r;
        arow = (l < cnt) ? (GATHER ? (long)g_slot_token[off + l] : (long)(off + l)) : -1;
    }
    bool av = (arow >= 0);
    const float* apf = A + (size_t)(av ? arow : 0) * lda + cq;
    const float* bpf = Bp + (size_t)(n0 + r) * K + cq;
    uint32_t sw = (uint32_t)(r * ROWB + cq * 2);   // 16B-aligned smem byte offset

    uint32_t sm0 = smem_u32(smem);

    // ---- ldmatrix per-thread bases ----
    int lane = tid & 31, wid = tid >> 5;
    int wm = wid & 3, wn = wid >> 2;               // warp grid 4(m) x 4(n)
    uint32_t lmoff = (uint32_t)((lane & 15) * ROWB + (lane >> 4) * 16);
    uint32_t aBase = sm0 + AH_OFF + (uint32_t)(wm * 32 * ROWB) + lmoff;
    uint32_t bBase = sm0 + BH_OFF + (uint32_t)(wn * 32 * ROWB) + lmoff;

    float c[2][4][4];
    #pragma unroll
    for (int i = 0; i < 2; i++)
        #pragma unroll
        for (int j = 0; j < 4; j++)
            #pragma unroll
            for (int q = 0; q < 4; q++) c[i][j][q] = 0.f;

    int KT = K / KC;
    const float4 z4 = make_float4(0.f, 0.f, 0.f, 0.f);
    float4 ra0, ra1, rb0, rb1;

    // prologue: chunk 0 -> regs -> stage 0
    ra0 = av ? *(const float4*)(apf + 0) : z4;
    ra1 = av ? *(const float4*)(apf + 4) : z4;
    rb0 = *(const float4*)(bpf + 0);
    rb1 = *(const float4*)(bpf + 4);
    {
        uint4 hi, lo;
        cvt8(ra0, ra1, hi, lo);
        *(uint4*)(smem + AH_OFF + sw) = hi;
        *(uint4*)(smem + AL_OFF + sw) = lo;
        cvt8(rb0, rb1, hi, lo);
        *(uint4*)(smem + BH_OFF + sw) = hi;
        *(uint4*)(smem + BL_OFF + sw) = lo;
    }

    for (int kt = 0; kt < KT; kt++) {
        __syncthreads();
        // issue global prefetch for chunk kt+1 (fills scoreboard, consumed after MMAs)
        bool more = (kt + 1 < KT);
        if (more) {
            const float* ap = apf + (kt + 1) * KC;
            const float* bp = bpf + (kt + 1) * KC;
            ra0 = av ? *(const float4*)(ap + 0) : z4;
            ra1 = av ? *(const float4*)(ap + 4) : z4;
            rb0 = *(const float4*)(bp + 0);
            rb1 = *(const float4*)(bp + 4);
        }

        // MMAs on current stage
        uint32_t st = (uint32_t)(kt & 1) * STAGE;
        uint32_t ab = aBase + st, bb = bBase + st;
        #pragma unroll
        for (int kk = 0; kk < 2; kk++) {
            uint32_t ah[2][4], al[2][4], bh[2][4], bl[2][4];
            #pragma unroll
            for (int mi = 0; mi < 2; mi++) {
                uint32_t ad = ab + mi * (16 * ROWB) + kk * 32;
                LDSM4(ah[mi], ad);
                LDSM4(al[mi], ad + (AL_OFF - AH_OFF));
            }
            #pragma unroll
            for (int j = 0; j < 2; j++) {
                uint32_t bd = bb + j * (16 * ROWB) + kk * 32;
                LDSM4(bh[j], bd);
                LDSM4(bl[j], bd + (BL_OFF - BH_OFF));
            }
            #pragma unroll
            for (int mi = 0; mi < 2; mi++) {
                #pragma unroll
                for (int ns = 0; ns < 4; ns++) {
                    int j = ns >> 1, sel = ns & 1;
                    MMA_BF16(c[mi][ns], ah[mi], bh[j][sel], bh[j][sel + 2]);
                    MMA_BF16(c[mi][ns], ah[mi], bl[j][sel], bl[j][sel + 2]);
                    MMA_BF16(c[mi][ns], al[mi], bh[j][sel], bh[j][sel + 2]);
                }
            }
        }

        // convert+store chunk kt+1 into the other stage (no barrier needed here:
        // next-iteration barrier orders it before anyone reads it)
        if (more) {
            char* sb = smem + ((kt + 1) & 1) * STAGE;
            uint4 hi, lo;
            cvt8(ra0, ra1, hi, lo);
            *(uint4*)(sb + AH_OFF + sw) = hi;
            *(uint4*)(sb + AL_OFF + sw) = lo;
            cvt8(rb0, rb1, hi, lo);
            *(uint4*)(sb + BH_OFF + sw) = hi;
            *(uint4*)(sb + BL_OFF + sw) = lo;
        }
    }

    // ---- epilogue ----
    #pragma unroll
    for (int mi = 0; mi < 2; mi++) {
        int lr0 = m0 + wm * 32 + mi * 16 + (lane >> 2);
        #pragma unroll
        for (int half = 0; half < 2; half++) {
            int lr = lr0 + half * 8;
            bool valid = !ROUTED || (lr < cnt);
            if (!valid) continue;
            int orow = ROUTED ? (off + lr) : lr;
            float s = 1.f;
            if (SCALEMODE == 1) s = g_slot_w[off + lr];
            if (SCALEMODE == 2) s = rscale[lr];
            float* cp = C + (size_t)orow * Ntot + n0 + wn * 32 + (lane & 3) * 2;
            #pragma unroll
            for (int ns = 0; ns < 4; ns++) {
                float2 v = make_float2(c[mi][ns][half * 2 + 0] * s,
                                       c[mi][ns][half * 2 + 1] * s);
                *(float2*)(cp + ns * 8) = v;
            }
        }
    }
}

// ================= launch =================
extern "C" void kernel_launch(void* const* d_in, const int* in_sizes, int n_in,
                              void* d_out, int out_size) {
    const float* x      = (const float*)d_in[0];
    const float* gate_w = (const float*)d_in[1];
    const float* sgw    = (const float*)d_in[2];
    const float* w13    = (const float*)d_in[3];
    const float* w2     = (const float*)d_in[4];
    const float* segu   = (const float*)d_in[5];
    const float* sedw   = (const float*)d_in[6];
    float* out = (float*)d_out;

    int M = in_sizes[0] / H;   // 1024

    float *gu_p, *hsh_p, *gur_p, *hr_p, *y_p, *sig_p;
    cudaGetSymbolAddress((void**)&gu_p,  g_gu);
    cudaGetSymbolAddress((void**)&hsh_p, g_hsh);
    cudaGetSymbolAddress((void**)&gur_p, g_gur);
    cudaGetSymbolAddress((void**)&hr_p,  g_hr);
    cudaGetSymbolAddress((void**)&y_p,   g_y);
    cudaGetSymbolAddress((void**)&sig_p, g_sig);

    cudaFuncSetAttribute(mma_gemm<0,0,0>, cudaFuncAttributeMaxDynamicSharedMemorySize, GEMM_SMEM);
    cudaFuncSetAttribute(mma_gemm<0,0,2>, cudaFuncAttributeMaxDynamicSharedMemorySize, GEMM_SMEM);
    cudaFuncSetAttribute(mma_gemm<1,1,0>, cudaFuncAttributeMaxDynamicSharedMemorySize, GEMM_SMEM);
    cudaFuncSetAttribute(mma_gemm<0,1,1>, cudaFuncAttributeMaxDynamicSharedMemorySize, GEMM_SMEM);

    // routing pipeline
    zero_counts_kernel<<<1, 64>>>();
    router_kernel<<<M, 256>>>(x, gate_w, sgw);
    scan_kernel<<<1, 32>>>();
    fill_kernel<<<(M + 255) / 256, 256>>>(M);

    // shared expert
    mma_gemm<0,0,0><<<dim3(ISH2 / 128, M / 128), 512, GEMM_SMEM>>>(
        x, H, segu, 0, gu_p, ISH2, H, nullptr);
    silu_mul_kernel<<<1024, 256>>>(gu_p, hsh_p, M, ISH, ISH2);
    mma_gemm<0,0,2><<<dim3(H / 128, M / 128), 512, GEMM_SMEM>>>(
        hsh_p, ISH, sedw, 0, out, H, ISH, sig_p);

    // routed experts
    int mtiles = M / 128;   // worst case: all tokens on one expert
    mma_gemm<1,1,0><<<dim3(I2 / 128, mtiles, E), 512, GEMM_SMEM>>>(
        x, H, w13, (size_t)I2 * H, gur_p, I2, H, nullptr);
    silu_mul_kernel<<<1024, 256>>>(gur_p, hr_p, M * TOPK, II, I2);
    mma_gemm<0,1,1><<<dim3(H / 128, mtiles, E), 512, GEMM_SMEM>>>(
        hr_p, II, w2, (size_t)H * II, y_p, H, II, nullptr);

    // deterministic per-token combine
    combine_kernel<<<M, 256>>>(out);
}

// round 5
// speedup vs baseline: 3.1643x; 1.2744x over previous
#include <cuda_runtime.h>
#include <cuda_fp16.h>
#include <math.h>
#include <stdint.h>
#include <string.h>

// ================= problem constants =================
#define H     2048
#define E     60
#define II    1408
#define I2    2816
#define ISH   5632
#define ISH2  11264
#define TOPK  4
#define MAXM  1024
#define MAXSLOTS (MAXM*TOPK)

// ================= device scratch =================
static __device__ float g_gu  [MAXM * ISH2];
static __device__ float g_hsh [MAXM * ISH];
static __device__ float g_gur [MAXSLOTS * I2];
static __device__ float g_hr  [MAXSLOTS * II];
static __device__ float g_y   [MAXSLOTS * H];
static __device__ float g_sig [MAXM];
static __device__ int   g_cnt [E];
static __device__ int   g_off [E];
static __device__ int   g_cur [E];
static __device__ int   g_slot_token[MAXSLOTS];
static __device__ float g_slot_w    [MAXSLOTS];
static __device__ int   g_slot_of   [MAXM * TOPK];
static __device__ int   g_tk_e      [MAXM * TOPK];
static __device__ float g_tk_w      [MAXM * TOPK];

// ================= small kernels =================
__global__ void zero_counts_kernel() {
    int t = threadIdx.x;
    if (t < E) g_cnt[t] = 0;
}

__global__ void router_kernel(const float* __restrict__ x,
                              const float* __restrict__ gate_w,
                              const float* __restrict__ sgw) {
    __shared__ float xs[H];
    __shared__ float logits[E + 1];
    int m = blockIdx.x;
    const float* xr = x + (size_t)m * H;
    for (int i = threadIdx.x; i < H; i += blockDim.x) xs[i] = xr[i];
    __syncthreads();

    int wid = threadIdx.x >> 5, lane = threadIdx.x & 31;
    for (int e = wid; e <= E; e += 8) {
        const float* wr = (e < E) ? (gate_w + (size_t)e * H) : sgw;
        float acc = 0.f;
        for (int k = lane; k < H; k += 32) acc += xs[k] * wr[k];
        #pragma unroll
        for (int o = 16; o; o >>= 1) acc += __shfl_xor_sync(0xffffffffu, acc, o);
        if (lane == 0) logits[e] = acc;
    }
    __syncthreads();

    if (threadIdx.x == 0) {
        g_sig[m] = 1.f / (1.f + expf(-logits[E]));
        float mx = -1e30f;
        for (int e = 0; e < E; e++) mx = fmaxf(mx, logits[e]);
        float sum = 0.f;
        for (int e = 0; e < E; e++) { float p = expf(logits[e] - mx); logits[e] = p; sum += p; }
        float inv = 1.f / sum;
        for (int k = 0; k < TOPK; k++) {
            int best = 0; float bv = -1.f;
            for (int e = 0; e < E; e++) { float v = logits[e]; if (v > bv) { bv = v; best = e; } }
            logits[best] = -2.f;
            g_tk_e[m * TOPK + k] = best;
            g_tk_w[m * TOPK + k] = bv * inv;
            atomicAdd(&g_cnt[best], 1);
        }
    }
}

__global__ void scan_kernel() {
    if (threadIdx.x == 0) {
        int s = 0;
        for (int e = 0; e < E; e++) { g_off[e] = s; s += g_cnt[e]; g_cur[e] = 0; }
    }
}

__global__ void fill_kernel(int M) {
    int m = blockIdx.x * blockDim.x + threadIdx.x;
    if (m >= M) return;
    for (int k = 0; k < TOPK; k++) {
        int e = g_tk_e[m * TOPK + k];
        int pos = atomicAdd(&g_cur[e], 1);
        int slot = g_off[e] + pos;
        g_slot_token[slot] = m;
        g_slot_w[slot] = g_tk_w[m * TOPK + k];
        g_slot_of[m * TOPK + k] = slot;
    }
}

__device__ __forceinline__ float silu_f(float v) { return v / (1.f + expf(-v)); }

__global__ void silu_mul_kernel(const float* __restrict__ gu, float* __restrict__ h,
                                int rows, int half, int full) {
    int total = rows * half;
    for (int idx = blockIdx.x * blockDim.x + threadIdx.x; idx < total;
         idx += gridDim.x * blockDim.x) {
        int r = idx / half, i = idx - r * half;
        float g = gu[(size_t)r * full + i];
        float u = gu[(size_t)r * full + half + i];
        h[(size_t)r * half + i] = silu_f(g) * u;
    }
}

__global__ void combine_kernel(float* __restrict__ out) {
    int m = blockIdx.x;
    int s0 = g_slot_of[m * TOPK + 0];
    int s1 = g_slot_of[m * TOPK + 1];
    int s2 = g_slot_of[m * TOPK + 2];
    int s3 = g_slot_of[m * TOPK + 3];
    for (int hcol = threadIdx.x; hcol < H; hcol += blockDim.x) {
        float v = out[(size_t)m * H + hcol];
        v += g_y[(size_t)s0 * H + hcol];
        v += g_y[(size_t)s1 * H + hcol];
        v += g_y[(size_t)s2 * H + hcol];
        v += g_y[(size_t)s3 * H + hcol];
        out[(size_t)m * H + hcol] = v;
    }
}

// ================= mma.sync GEMM (fp16 2-pass: A split hi/lo, B single) =====
// C[M,N] = A[M,K] @ B[N,K]^T in fp32. a = ah + al (fp16 exact residual);
// C = (ah + al) @ bh  -> only error is B's fp16 rounding (~1.6e-4 norm).
// Tile 128x128, KC=64 fp32/chunk, 512 threads (16 warps, 4x4), warp tile 32x32.
// 2-stage SMEM ring, ONE __syncthreads per chunk.
#define KC       64
#define ROWB     144                // 64 halves + 8 pad
#define SUBT     (128 * ROWB)       // 18432 B
#define AH_OFF   0
#define AL_OFF   (1 * SUBT)
#define BH_OFF   (2 * SUBT)
#define STAGE    (3 * SUBT)         // 55296 B
#define GEMM_SMEM (2 * STAGE)       // 110592 B

__device__ __forceinline__ uint32_t smem_u32(const void* p) {
    uint32_t a;
    asm("{ .reg .u64 t; cvta.to.shared.u64 t, %1; cvt.u32.u64 %0, t; }" : "=r"(a) : "l"(p));
    return a;
}
__device__ __forceinline__ uint32_t h2u(__half2 h) {
    uint32_t u; memcpy(&u, &h, 4); return u;
}

#define LDSM4(r, addr) \
    asm volatile("ldmatrix.sync.aligned.m8n8.x4.shared.b16 {%0,%1,%2,%3}, [%4];" \
        : "=r"((r)[0]), "=r"((r)[1]), "=r"((r)[2]), "=r"((r)[3]) : "r"(addr))

#define MMA_F16(c, a, b0, b1) \
    asm volatile("mma.sync.aligned.m16n8k16.row.col.f32.f16.f16.f32 " \
        "{%0,%1,%2,%3}, {%4,%5,%6,%7}, {%8,%9}, {%0,%1,%2,%3};" \
        : "+f"((c)[0]), "+f"((c)[1]), "+f"((c)[2]), "+f"((c)[3]) \
        : "r"((a)[0]), "r"((a)[1]), "r"((a)[2]), "r"((a)[3]), "r"(b0), "r"(b1))

// 8 fp32 -> 8 fp16 hi + 8 fp16 lo (exact residual), memory order preserved.
__device__ __forceinline__ void cvtA8(float4 v0, float4 v1, uint4& hi, uint4& lo) {
    __half2 h0 = __floats2half2_rn(v0.x, v0.y);
    __half2 h1 = __floats2half2_rn(v0.z, v0.w);
    __half2 h2 = __floats2half2_rn(v1.x, v1.y);
    __half2 h3 = __floats2half2_rn(v1.z, v1.w);
    float2 f0 = __half22float2(h0);
    float2 f1 = __half22float2(h1);
    float2 f2 = __half22float2(h2);
    float2 f3 = __half22float2(h3);
    __half2 l0 = __floats2half2_rn(v0.x - f0.x, v0.y - f0.y);
    __half2 l1 = __floats2half2_rn(v0.z - f1.x, v0.w - f1.y);
    __half2 l2 = __floats2half2_rn(v1.x - f2.x, v1.y - f2.y);
    __half2 l3 = __floats2half2_rn(v1.z - f3.x, v1.w - f3.y);
    hi = make_uint4(h2u(h0), h2u(h1), h2u(h2), h2u(h3));
    lo = make_uint4(h2u(l0), h2u(l1), h2u(l2), h2u(l3));
}
// 8 fp32 -> 8 fp16 (single rounding).
__device__ __forceinline__ uint4 cvtB8(float4 v0, float4 v1) {
    __half2 h0 = __floats2half2_rn(v0.x, v0.y);
    __half2 h1 = __floats2half2_rn(v0.z, v0.w);
    __half2 h2 = __floats2half2_rn(v1.x, v1.y);
    __half2 h3 = __floats2half2_rn(v1.z, v1.w);
    return make_uint4(h2u(h0), h2u(h1), h2u(h2), h2u(h3));
}

// GATHER: A row via g_slot_token[off+l]; ROUTED: grid.z = expert.
// SCALEMODE: 0 none, 1 g_slot_w[slot], 2 rscale[row].
template<int GATHER, int ROUTED, int SCALEMODE>
__global__ void __launch_bounds__(512, 1) mma_gemm(
    const float* __restrict__ A, int lda,
    const float* __restrict__ Bbase, size_t strideB,
    float* __restrict__ C, int Ntot, int K,
    const float* __restrict__ rscale)
{
    extern __shared__ char smem[];
    int cnt = 0x3fffffff, off = 0, m0 = blockIdx.y * 128;
    const float* Bp = Bbase;
    if (ROUTED) {
        int e = blockIdx.z;
        cnt = g_cnt[e];
        if (m0 >= cnt) return;
        off = g_off[e];
        Bp += (size_t)e * strideB;
    }
    int n0 = blockIdx.x * 128;
    int tid = threadIdx.x;

    // ---- load mapping: thread t -> row r = t>>2, fp32 cols cq..cq+7 and cq+32..cq+39 ----
    int r = tid >> 2;
    int cq = (tid & 3) << 3;
    long arow;
    if (!ROUTED) arow = m0 + r;
    else {
        int l = m0 + r;
        arow = (l < cnt) ? (GATHER ? (long)g_slot_token[off + l] : (long)(off + l)) : -1;
    }
    bool av = (arow >= 0);
    const float* apf = A + (size_t)(av ? arow : 0) * lda + cq;
    const float* bpf = Bp + (size_t)(n0 + r) * K + cq;
    uint32_t sw0 = (uint32_t)(r * ROWB + cq * 2);    // halves 0..31
    uint32_t sw1 = sw0 + 64;                          // halves 32..63

    uint32_t sm0 = smem_u32(smem);

    // ---- ldmatrix per-thread bases ----
    int lane = tid & 31, wid = tid >> 5;
    int wm = wid & 3, wn = wid >> 2;                  // warp grid 4(m) x 4(n)
    uint32_t lmoff = (uint32_t)((lane & 15) * ROWB + (lane >> 4) * 16);
    uint32_t aBase = sm0 + AH_OFF + (uint32_t)(wm * 32 * ROWB) + lmoff;
    uint32_t bBase = sm0 + BH_OFF + (uint32_t)(wn * 32 * ROWB) + lmoff;

    float c[2][4][4];
    #pragma unroll
    for (int i = 0; i < 2; i++)
        #pragma unroll
        for (int j = 0; j < 4; j++)
            #pragma unroll
            for (int q = 0; q < 4; q++) c[i][j][q] = 0.f;

    int KT = K / KC;
    const float4 z4 = make_float4(0.f, 0.f, 0.f, 0.f);
    float4 ra[4], rb[4];

    // prologue: chunk 0 -> regs -> stage 0
    #pragma unroll
    for (int q = 0; q < 2; q++) {
        ra[2*q+0] = av ? *(const float4*)(apf + 32*q + 0) : z4;
        ra[2*q+1] = av ? *(const float4*)(apf + 32*q + 4) : z4;
        rb[2*q+0] = *(const float4*)(bpf + 32*q + 0);
        rb[2*q+1] = *(const float4*)(bpf + 32*q + 4);
    }
    {
        uint4 hi, lo;
        cvtA8(ra[0], ra[1], hi, lo);
        *(uint4*)(smem + AH_OFF + sw0) = hi;
        *(uint4*)(smem + AL_OFF + sw0) = lo;
        cvtA8(ra[2], ra[3], hi, lo);
        *(uint4*)(smem + AH_OFF + sw1) = hi;
        *(uint4*)(smem + AL_OFF + sw1) = lo;
        *(uint4*)(smem + BH_OFF + sw0) = cvtB8(rb[0], rb[1]);
        *(uint4*)(smem + BH_OFF + sw1) = cvtB8(rb[2], rb[3]);
    }

    for (int kt = 0; kt < KT; kt++) {
        __syncthreads();
        bool more = (kt + 1 < KT);
        if (more) {
            const float* ap = apf + (kt + 1) * KC;
            const float* bp = bpf + (kt + 1) * KC;
            #pragma unroll
            for (int q = 0; q < 2; q++) {
                ra[2*q+0] = av ? *(const float4*)(ap + 32*q + 0) : z4;
                ra[2*q+1] = av ? *(const float4*)(ap + 32*q + 4) : z4;
                rb[2*q+0] = *(const float4*)(bp + 32*q + 0);
                rb[2*q+1] = *(const float4*)(bp + 32*q + 4);
            }
        }

        // MMAs on current stage
        uint32_t st = (uint32_t)(kt & 1) * STAGE;
        uint32_t ab = aBase + st, bb = bBase + st;
        #pragma unroll
        for (int kk = 0; kk < 4; kk++) {
            uint32_t ah[2][4], al[2][4], bh[2][4];
            #pragma unroll
            for (int mi = 0; mi < 2; mi++) {
                uint32_t ad = ab + mi * (16 * ROWB) + kk * 32;
                LDSM4(ah[mi], ad);
                LDSM4(al[mi], ad + (AL_OFF - AH_OFF));
            }
            #pragma unroll
            for (int j = 0; j < 2; j++) {
                uint32_t bd = bb + j * (16 * ROWB) + kk * 32;
                LDSM4(bh[j], bd);
            }
            #pragma unroll
            for (int mi = 0; mi < 2; mi++) {
                #pragma unroll
                for (int ns = 0; ns < 4; ns++) {
                    int j = ns >> 1, sel = ns & 1;
                    MMA_F16(c[mi][ns], ah[mi], bh[j][sel], bh[j][sel + 2]);
                    MMA_F16(c[mi][ns], al[mi], bh[j][sel], bh[j][sel + 2]);
                }
            }
        }

        // convert+store chunk kt+1 into the other stage
        if (more) {
            char* sb = smem + ((kt + 1) & 1) * STAGE;
            uint4 hi, lo;
            cvtA8(ra[0], ra[1], hi, lo);
            *(uint4*)(sb + AH_OFF + sw0) = hi;
            *(uint4*)(sb + AL_OFF + sw0) = lo;
            cvtA8(ra[2], ra[3], hi, lo);
            *(uint4*)(sb + AH_OFF + sw1) = hi;
            *(uint4*)(sb + AL_OFF + sw1) = lo;
            *(uint4*)(sb + BH_OFF + sw0) = cvtB8(rb[0], rb[1]);
            *(uint4*)(sb + BH_OFF + sw1) = cvtB8(rb[2], rb[3]);
        }
    }

    // ---- epilogue ----
    #pragma unroll
    for (int mi = 0; mi < 2; mi++) {
        int lr0 = m0 + wm * 32 + mi * 16 + (lane >> 2);
        #pragma unroll
        for (int half = 0; half < 2; half++) {
            int lr = lr0 + half * 8;
            bool valid = !ROUTED || (lr < cnt);
            if (!valid) continue;
            int orow = ROUTED ? (off + lr) : lr;
            float s = 1.f;
            if (SCALEMODE == 1) s = g_slot_w[off + lr];
            if (SCALEMODE == 2) s = rscale[lr];
            float* cp = C + (size_t)orow * Ntot + n0 + wn * 32 + (lane & 3) * 2;
            #pragma unroll
            for (int ns = 0; ns < 4; ns++) {
                float2 v = make_float2(c[mi][ns][half * 2 + 0] * s,
                                       c[mi][ns][half * 2 + 1] * s);
                *(float2*)(cp + ns * 8) = v;
            }
        }
    }
}

// ================= launch =================
extern "C" void kernel_launch(void* const* d_in, const int* in_sizes, int n_in,
                              void* d_out, int out_size) {
    const float* x      = (const float*)d_in[0];
    const float* gate_w = (const float*)d_in[1];
    const float* sgw    = (const float*)d_in[2];
    const float* w13    = (const float*)d_in[3];
    const float* w2     = (const float*)d_in[4];
    const float* segu   = (const float*)d_in[5];
    const float* sedw   = (const float*)d_in[6];
    float* out = (float*)d_out;

    int M = in_sizes[0] / H;   // 1024

    float *gu_p, *hsh_p, *gur_p, *hr_p, *y_p, *sig_p;
    cudaGetSymbolAddress((void**)&gu_p,  g_gu);
    cudaGetSymbolAddress((void**)&hsh_p, g_hsh);
    cudaGetSymbolAddress((void**)&gur_p, g_gur);
    cudaGetSymbolAddress((void**)&hr_p,  g_hr);
    cudaGetSymbolAddress((void**)&y_p,   g_y);
    cudaGetSymbolAddress((void**)&sig_p, g_sig);

    cudaFuncSetAttribute(mma_gemm<0,0,0>, cudaFuncAttributeMaxDynamicSharedMemorySize, GEMM_SMEM);
    cudaFuncSetAttribute(mma_gemm<0,0,2>, cudaFuncAttributeMaxDynamicSharedMemorySize, GEMM_SMEM);
    cudaFuncSetAttribute(mma_gemm<1,1,0>, cudaFuncAttributeMaxDynamicSharedMemorySize, GEMM_SMEM);
    cudaFuncSetAttribute(mma_gemm<0,1,1>, cudaFuncAttributeMaxDynamicSharedMemorySize, GEMM_SMEM);

    // routing pipeline
    zero_counts_kernel<<<1, 64>>>();
    router_kernel<<<M, 256>>>(x, gate_w, sgw);
    scan_kernel<<<1, 32>>>();
    fill_kernel<<<(M + 255) / 256, 256>>>(M);

    // shared expert
    mma_gemm<0,0,0><<<dim3(ISH2 / 128, M / 128), 512, GEMM_SMEM>>>(
        x, H, segu, 0, gu_p, ISH2, H, nullptr);
    silu_mul_kernel<<<1024, 256>>>(gu_p, hsh_p, M, ISH, ISH2);
    mma_gemm<0,0,2><<<dim3(H / 128, M / 128), 512, GEMM_SMEM>>>(
        hsh_p, ISH, sedw, 0, out, H, ISH, sig_p);

    // routed experts
    int mtiles = M / 128;   // worst case: all tokens on one expert
    mma_gemm<1,1,0><<<dim3(I2 / 128, mtiles, E), 512, GEMM_SMEM>>>(
        x, H, w13, (size_t)I2 * H, gur_p, I2, H, nullptr);
    silu_mul_kernel<<<1024, 256>>>(gur_p, hr_p, M * TOPK, II, I2);
    mma_gemm<0,1,1><<<dim3(H / 128, mtiles, E), 512, GEMM_SMEM>>>(
        hr_p, II, w2, (size_t)H * II, y_p, H, II, nullptr);

    // deterministic per-token combine
    combine_kernel<<<M, 256>>>(out);
}

// round 6
// speedup vs baseline: 3.7056x; 1.1711x over previous
#include <cuda_runtime.h>
#include <cuda_fp16.h>
#include <math.h>
#include <stdint.h>
#include <string.h>

// ================= problem constants =================
#define H     2048
#define E     60
#define II    1408
#define I2    2816
#define ISH   5632
#define ISH2  11264
#define TOPK  4
#define MAXM  1024
#define MAXSLOTS (MAXM*TOPK)

// ================= device scratch =================
static __device__ float g_gu  [MAXM * ISH2];
static __device__ float g_hsh [MAXM * ISH];
static __device__ float g_gur [MAXSLOTS * I2];
static __device__ float g_hr  [MAXSLOTS * II];
static __device__ float g_y   [MAXSLOTS * H];
static __device__ float g_sig [MAXM];
static __device__ int   g_cnt [E];
static __device__ int   g_off [E];
static __device__ int   g_cur [E];
static __device__ int   g_slot_token[MAXSLOTS];
static __device__ float g_slot_w    [MAXSLOTS];
static __device__ int   g_slot_of   [MAXM * TOPK];
static __device__ int   g_tk_e      [MAXM * TOPK];
static __device__ float g_tk_w      [MAXM * TOPK];

// ================= small kernels =================
__global__ void zero_counts_kernel() {
    int t = threadIdx.x;
    if (t < E) g_cnt[t] = 0;
}

__global__ void router_kernel(const float* __restrict__ x,
                              const float* __restrict__ gate_w,
                              const float* __restrict__ sgw) {
    __shared__ float xs[H];
    __shared__ float logits[E + 1];
    int m = blockIdx.x;
    const float* xr = x + (size_t)m * H;
    for (int i = threadIdx.x; i < H; i += blockDim.x) xs[i] = xr[i];
    __syncthreads();

    int wid = threadIdx.x >> 5, lane = threadIdx.x & 31;
    for (int e = wid; e <= E; e += 8) {
        const float* wr = (e < E) ? (gate_w + (size_t)e * H) : sgw;
        float acc = 0.f;
        for (int k = lane; k < H; k += 32) acc += xs[k] * wr[k];
        #pragma unroll
        for (int o = 16; o; o >>= 1) acc += __shfl_xor_sync(0xffffffffu, acc, o);
        if (lane == 0) logits[e] = acc;
    }
    __syncthreads();

    if (threadIdx.x == 0) {
        g_sig[m] = 1.f / (1.f + expf(-logits[E]));
        float mx = -1e30f;
        for (int e = 0; e < E; e++) mx = fmaxf(mx, logits[e]);
        float sum = 0.f;
        for (int e = 0; e < E; e++) { float p = expf(logits[e] - mx); logits[e] = p; sum += p; }
        float inv = 1.f / sum;
        for (int k = 0; k < TOPK; k++) {
            int best = 0; float bv = -1.f;
            for (int e = 0; e < E; e++) { float v = logits[e]; if (v > bv) { bv = v; best = e; } }
            logits[best] = -2.f;
            g_tk_e[m * TOPK + k] = best;
            g_tk_w[m * TOPK + k] = bv * inv;
            atomicAdd(&g_cnt[best], 1);
        }
    }
}

__global__ void scan_kernel() {
    if (threadIdx.x == 0) {
        int s = 0;
        for (int e = 0; e < E; e++) { g_off[e] = s; s += g_cnt[e]; g_cur[e] = 0; }
    }
}

__global__ void fill_kernel(int M) {
    int m = blockIdx.x * blockDim.x + threadIdx.x;
    if (m >= M) return;
    for (int k = 0; k < TOPK; k++) {
        int e = g_tk_e[m * TOPK + k];
        int pos = atomicAdd(&g_cur[e], 1);
        int slot = g_off[e] + pos;
        g_slot_token[slot] = m;
        g_slot_w[slot] = g_tk_w[m * TOPK + k];
        g_slot_of[m * TOPK + k] = slot;
    }
}

__device__ __forceinline__ float silu_f(float v) { return v / (1.f + expf(-v)); }

__global__ void silu_mul_kernel(const float* __restrict__ gu, float* __restrict__ h,
                                int rows, int half, int full) {
    int total = rows * half;
    for (int idx = blockIdx.x * blockDim.x + threadIdx.x; idx < total;
         idx += gridDim.x * blockDim.x) {
        int r = idx / half, i = idx - r * half;
        float g = gu[(size_t)r * full + i];
        float u = gu[(size_t)r * full + half + i];
        h[(size_t)r * half + i] = silu_f(g) * u;
    }
}

__global__ void combine_kernel(float* __restrict__ out) {
    int m = blockIdx.x;
    int s0 = g_slot_of[m * TOPK + 0];
    int s1 = g_slot_of[m * TOPK + 1];
    int s2 = g_slot_of[m * TOPK + 2];
    int s3 = g_slot_of[m * TOPK + 3];
    for (int hcol = threadIdx.x; hcol < H; hcol += blockDim.x) {
        float v = out[(size_t)m * H + hcol];
        v += g_y[(size_t)s0 * H + hcol];
        v += g_y[(size_t)s1 * H + hcol];
        v += g_y[(size_t)s2 * H + hcol];
        v += g_y[(size_t)s3 * H + hcol];
        out[(size_t)m * H + hcol] = v;
    }
}

// ================= mma.sync GEMM (single-pass fp16, fp32 accum) =================
// C[M,N] = A[M,K] @ B[N,K]^T. Tile MTILE x 128 (MTILE = MI*64), KC=64 fp32/chunk,
// 512 threads (16 warps, 4(m) x 4(n)), warp tile (MI*16) x 32.
// 2-stage SMEM ring, ONE __syncthreads per chunk.
#define KC       64
#define ROWB     144                // 64 halves + 8 pad

__device__ __forceinline__ uint32_t smem_u32(const void* p) {
    uint32_t a;
    asm("{ .reg .u64 t; cvta.to.shared.u64 t, %1; cvt.u32.u64 %0, t; }" : "=r"(a) : "l"(p));
    return a;
}
__device__ __forceinline__ uint32_t h2u(__half2 h) {
    uint32_t u; memcpy(&u, &h, 4); return u;
}

#define LDSM4(r, addr) \
    asm volatile("ldmatrix.sync.aligned.m8n8.x4.shared.b16 {%0,%1,%2,%3}, [%4];" \
        : "=r"((r)[0]), "=r"((r)[1]), "=r"((r)[2]), "=r"((r)[3]) : "r"(addr))

#define MMA_F16(c, a, b0, b1) \
    asm volatile("mma.sync.aligned.m16n8k16.row.col.f32.f16.f16.f32 " \
        "{%0,%1,%2,%3}, {%4,%5,%6,%7}, {%8,%9}, {%0,%1,%2,%3};" \
        : "+f"((c)[0]), "+f"((c)[1]), "+f"((c)[2]), "+f"((c)[3]) \
        : "r"((a)[0]), "r"((a)[1]), "r"((a)[2]), "r"((a)[3]), "r"(b0), "r"(b1))

// 8 fp32 -> 8 fp16 (single rounding), memory order preserved.
__device__ __forceinline__ uint4 cvt8(float4 v0, float4 v1) {
    __half2 h0 = __floats2half2_rn(v0.x, v0.y);
    __half2 h1 = __floats2half2_rn(v0.z, v0.w);
    __half2 h2 = __floats2half2_rn(v1.x, v1.y);
    __half2 h3 = __floats2half2_rn(v1.z, v1.w);
    return make_uint4(h2u(h0), h2u(h1), h2u(h2), h2u(h3));
}

// MI: 2 -> 128-row tile, 1 -> 64-row tile (routed; less padding waste).
// GATHER: A row via g_slot_token[off+l]; ROUTED: grid.z = expert.
// SCALEMODE: 0 none, 1 g_slot_w[slot], 2 rscale[row].
template<int MI, int GATHER, int ROUTED, int SCALEMODE>
__global__ void __launch_bounds__(512, 1) mma_gemm(
    const float* __restrict__ A, int lda,
    const float* __restrict__ Bbase, size_t strideB,
    float* __restrict__ C, int Ntot, int K,
    const float* __restrict__ rscale)
{
    constexpr int MTILE   = MI * 64;
    constexpr int A_BYTES = MTILE * ROWB;
    constexpr int STAGE   = (MTILE + 128) * ROWB;

    extern __shared__ char smem[];
    int cnt = 0x3fffffff, off = 0, m0 = blockIdx.y * MTILE;
    const float* Bp = Bbase;
    if (ROUTED) {
        int e = blockIdx.z;
        cnt = g_cnt[e];
        if (m0 >= cnt) return;
        off = g_off[e];
        Bp += (size_t)e * strideB;
    }
    int n0 = blockIdx.x * 128;
    int tid = threadIdx.x;

    // ---- A loader mapping ----
    int rA, cqA;
    if (MI == 2) { rA = tid >> 2; cqA = (tid & 3) << 3; }    // 128 rows, 2 groups
    else         { rA = tid >> 3; cqA = (tid & 7) << 3; }    // 64 rows, 1 group
    long arow;
    if (!ROUTED) arow = m0 + rA;
    else {
        int l = m0 + rA;
        arow = (l < cnt) ? (GATHER ? (long)g_slot_token[off + l] : (long)(off + l)) : -1;
    }
    bool av = (arow >= 0);
    const float* apf = A + (size_t)(av ? arow : 0) * lda + cqA;
    uint32_t swA0 = (uint32_t)(rA * ROWB + cqA * 2);
    uint32_t swA1 = swA0 + 64;            // MI==2 only (cols 32..63)

    // ---- B loader mapping (always 128 rows, 2 groups) ----
    int rB = tid >> 2, cqB = (tid & 3) << 3;
    const float* bpf = Bp + (size_t)(n0 + rB) * K + cqB;
    uint32_t swB0 = (uint32_t)(A_BYTES + rB * ROWB + cqB * 2);
    uint32_t swB1 = swB0 + 64;

    uint32_t sm0 = smem_u32(smem);

    // ---- ldmatrix per-thread bases ----
    int lane = tid & 31, wid = tid >> 5;
    int wm = wid & 3, wn = wid >> 2;                  // warp grid 4(m) x 4(n)
    uint32_t lmoff = (uint32_t)((lane & 15) * ROWB + (lane >> 4) * 16);
    uint32_t aBase = sm0 + (uint32_t)(wm * (MI * 16) * ROWB) + lmoff;
    uint32_t bBase = sm0 + A_BYTES + (uint32_t)(wn * 32 * ROWB) + lmoff;

    float c[MI][4][4];
    #pragma unroll
    for (int i = 0; i < MI; i++)
        #pragma unroll
        for (int j = 0; j < 4; j++)
            #pragma unroll
            for (int q = 0; q < 4; q++) c[i][j][q] = 0.f;

    int KT = K / KC;
    const float4 z4 = make_float4(0.f, 0.f, 0.f, 0.f);
    float4 ra[4], rb[4];

    // prologue: chunk 0 -> regs -> stage 0
    ra[0] = av ? *(const float4*)(apf + 0) : z4;
    ra[1] = av ? *(const float4*)(apf + 4) : z4;
    if (MI == 2) {
        ra[2] = av ? *(const float4*)(apf + 32) : z4;
        ra[3] = av ? *(const float4*)(apf + 36) : z4;
    }
    #pragma unroll
    for (int q = 0; q < 2; q++) {
        rb[2*q+0] = *(const float4*)(bpf + 32*q + 0);
        rb[2*q+1] = *(const float4*)(bpf + 32*q + 4);
    }
    {
        *(uint4*)(smem + swA0) = cvt8(ra[0], ra[1]);
        if (MI == 2) *(uint4*)(smem + swA1) = cvt8(ra[2], ra[3]);
        *(uint4*)(smem + swB0) = cvt8(rb[0], rb[1]);
        *(uint4*)(smem + swB1) = cvt8(rb[2], rb[3]);
    }

    for (int kt = 0; kt < KT; kt++) {
        __syncthreads();
        bool more = (kt + 1 < KT);
        if (more) {
            const float* ap = apf + (kt + 1) * KC;
            const float* bp = bpf + (kt + 1) * KC;
            ra[0] = av ? *(const float4*)(ap + 0) : z4;
            ra[1] = av ? *(const float4*)(ap + 4) : z4;
            if (MI == 2) {
                ra[2] = av ? *(const float4*)(ap + 32) : z4;
                ra[3] = av ? *(const float4*)(ap + 36) : z4;
            }
            #pragma unroll
            for (int q = 0; q < 2; q++) {
                rb[2*q+0] = *(const float4*)(bp + 32*q + 0);
                rb[2*q+1] = *(const float4*)(bp + 32*q + 4);
            }
        }

        // MMAs on current stage
        uint32_t st = (uint32_t)(kt & 1) * STAGE;
        uint32_t ab = aBase + st, bb = bBase + st;
        #pragma unroll
        for (int kk = 0; kk < 4; kk++) {
            uint32_t ah[MI][4], bh[2][4];
            #pragma unroll
            for (int mi = 0; mi < MI; mi++)
                LDSM4(ah[mi], ab + mi * (16 * ROWB) + kk * 32);
            #pragma unroll
            for (int j = 0; j < 2; j++)
                LDSM4(bh[j], bb + j * (16 * ROWB) + kk * 32);
            #pragma unroll
            for (int mi = 0; mi < MI; mi++) {
                #pragma unroll
                for (int ns = 0; ns < 4; ns++) {
                    int j = ns >> 1, sel = ns & 1;
                    MMA_F16(c[mi][ns], ah[mi], bh[j][sel], bh[j][sel + 2]);
                }
            }
        }

        // convert+store chunk kt+1 into the other stage
        if (more) {
            char* sb = smem + ((kt + 1) & 1) * STAGE;
            *(uint4*)(sb + swA0) = cvt8(ra[0], ra[1]);
            if (MI == 2) *(uint4*)(sb + swA1) = cvt8(ra[2], ra[3]);
            *(uint4*)(sb + swB0) = cvt8(rb[0], rb[1]);
            *(uint4*)(sb + swB1) = cvt8(rb[2], rb[3]);
        }
    }

    // ---- epilogue ----
    #pragma unroll
    for (int mi = 0; mi < MI; mi++) {
        int lr0 = m0 + wm * (MI * 16) + mi * 16 + (lane >> 2);
        #pragma unroll
        for (int half = 0; half < 2; half++) {
            int lr = lr0 + half * 8;
            bool valid = !ROUTED || (lr < cnt);
            if (!valid) continue;
            int orow = ROUTED ? (off + lr) : lr;
            float s = 1.f;
            if (SCALEMODE == 1) s = g_slot_w[off + lr];
            if (SCALEMODE == 2) s = rscale[lr];
            float* cp = C + (size_t)orow * Ntot + n0 + wn * 32 + (lane & 3) * 2;
            #pragma unroll
            for (int ns = 0; ns < 4; ns++) {
                float2 v = make_float2(c[mi][ns][half * 2 + 0] * s,
                                       c[mi][ns][half * 2 + 1] * s);
                *(float2*)(cp + ns * 8) = v;
            }
        }
    }
}

// ================= launch =================
extern "C" void kernel_launch(void* const* d_in, const int* in_sizes, int n_in,
                              void* d_out, int out_size) {
    const float* x      = (const float*)d_in[0];
    const float* gate_w = (const float*)d_in[1];
    const float* sgw    = (const float*)d_in[2];
    const float* w13    = (const float*)d_in[3];
    const float* w2     = (const float*)d_in[4];
    const float* segu   = (const float*)d_in[5];
    const float* sedw   = (const float*)d_in[6];
    float* out = (float*)d_out;

    int M = in_sizes[0] / H;   // 1024

    float *gu_p, *hsh_p, *gur_p, *hr_p, *y_p, *sig_p;
    cudaGetSymbolAddress((void**)&gu_p,  g_gu);
    cudaGetSymbolAddress((void**)&hsh_p, g_hsh);
    cudaGetSymbolAddress((void**)&gur_p, g_gur);
    cudaGetSymbolAddress((void**)&hr_p,  g_hr);
    cudaGetSymbolAddress((void**)&y_p,   g_y);
    cudaGetSymbolAddress((void**)&sig_p, g_sig);

    const int SMEM_M128 = 2 * (256 * ROWB);   // 73728
    const int SMEM_M64  = 2 * (192 * ROWB);   // 55296

    cudaFuncSetAttribute(mma_gemm<2,0,0,0>, cudaFuncAttributeMaxDynamicSharedMemorySize, SMEM_M128);
    cudaFuncSetAttribute(mma_gemm<2,0,0,2>, cudaFuncAttributeMaxDynamicSharedMemorySize, SMEM_M128);
    cudaFuncSetAttribute(mma_gemm<1,1,1,0>, cudaFuncAttributeMaxDynamicSharedMemorySize, SMEM_M64);
    cudaFuncSetAttribute(mma_gemm<1,0,1,1>, cudaFuncAttributeMaxDynamicSharedMemorySize, SMEM_M64);

    // routing pipeline
    zero_counts_kernel<<<1, 64>>>();
    router_kernel<<<M, 256>>>(x, gate_w, sgw);
    scan_kernel<<<1, 32>>>();
    fill_kernel<<<(M + 255) / 256, 256>>>(M);

    // shared expert (dense, 128-row tiles)
    mma_gemm<2,0,0,0><<<dim3(ISH2 / 128, M / 128), 512, SMEM_M128>>>(
        x, H, segu, 0, gu_p, ISH2, H, nullptr);
    silu_mul_kernel<<<1024, 256>>>(gu_p, hsh_p, M, ISH, ISH2);
    mma_gemm<2,0,0,2><<<dim3(H / 128, M / 128), 512, SMEM_M128>>>(
        hsh_p, ISH, sedw, 0, out, H, ISH, sig_p);

    // routed experts (64-row tiles to cut padding)
    int mtiles = M / 64;   // worst case: all tokens on one expert
    mma_gemm<1,1,1,0><<<dim3(I2 / 128, mtiles, E), 512, SMEM_M64>>>(
        x, H, w13, (size_t)I2 * H, gur_p, I2, H, nullptr);
    silu_mul_kernel<<<1024, 256>>>(gur_p, hr_p, M * TOPK, II, I2);
    mma_gemm<1,0,1,1><<<dim3(H / 128, mtiles, E), 512, SMEM_M64>>>(
        hr_p, II, w2, (size_t)H * II, y_p, H, II, nullptr);

    // deterministic per-token combine
    combine_kernel<<<M, 256>>>(out);
}